// round 4
// baseline (speedup 1.0000x reference)
#include <cuda_runtime.h>
#include <cuda_bf16.h>

#define T_STEPS 1000
#define BETA_1 1e-4
#define BETA_T 0.02

// ---- compile-time table: (sqrt(alpha_bar[t]), sqrt(1-alpha_bar[t])) ----

struct ScaleTable {
    float2 v[T_STEPS];
};

constexpr double csqrt(double x) {
    double g = x > 1.0 ? x : 1.0;
    for (int i = 0; i < 60; ++i) g = 0.5 * (g + x / g);
    return g;
}

constexpr ScaleTable make_table() {
    ScaleTable tbl{};
    const double slope = (BETA_T - BETA_1) / (double)(T_STEPS - 1);
    double ab = 1.0;
    for (int i = 0; i < T_STEPS; ++i) {
        double beta = BETA_1 + slope * (double)i;
        ab *= (1.0 - beta);
        tbl.v[i].x = (float)csqrt(ab);
        tbl.v[i].y = (float)csqrt(1.0 - ab);
    }
    return tbl;
}

__constant__ ScaleTable g_scales = make_table();

// ---- mix kernel: 2 float4 per thread (offset-split), streaming hints ----
// total4 = B * 196. Thread handles idx and idx + half (half = ceil(total4/2)).
// All 4 loads issued up front for max MLP; every LDG/STG fully coalesced.

__global__ void __launch_bounds__(256) ddpm_mix_kernel(
    const float4* __restrict__ images,
    const float4* __restrict__ e,
    const int* __restrict__ t,
    float4* __restrict__ out,
    int half, int total4)
{
    const int i0 = blockIdx.x * 256 + threadIdx.x;
    if (i0 >= half) return;
    const int i1 = i0 + half;
    const bool has1 = (i1 < total4);

    // Front-batch all global loads (MLP=4..6)
    float4 im0 = __ldcs(&images[i0]);
    float4 ee0 = __ldcs(&e[i0]);
    float4 im1, ee1;
    if (has1) {
        im1 = __ldcs(&images[i1]);
        ee1 = __ldcs(&e[i1]);
    }

    const unsigned b0 = (unsigned)i0 / 196u;
    const int ti0 = __ldg(&t[b0]);
    const float2 sc0 = g_scales.v[ti0];

    float4 o0;
    o0.x = fmaf(sc0.x, im0.x, sc0.y * ee0.x);
    o0.y = fmaf(sc0.x, im0.y, sc0.y * ee0.y);
    o0.z = fmaf(sc0.x, im0.z, sc0.y * ee0.z);
    o0.w = fmaf(sc0.x, im0.w, sc0.y * ee0.w);
    __stcs(&out[i0], o0);

    if (has1) {
        const unsigned b1 = (unsigned)i1 / 196u;
        const int ti1 = __ldg(&t[b1]);
        const float2 sc1 = g_scales.v[ti1];
        float4 o1;
        o1.x = fmaf(sc1.x, im1.x, sc1.y * ee1.x);
        o1.y = fmaf(sc1.x, im1.y, sc1.y * ee1.y);
        o1.z = fmaf(sc1.x, im1.z, sc1.y * ee1.z);
        o1.w = fmaf(sc1.x, im1.w, sc1.y * ee1.w);
        __stcs(&out[i1], o1);
    }
}

extern "C" void kernel_launch(void* const* d_in, const int* in_sizes, int n_in,
                              void* d_out, int out_size) {
    const float4* images = (const float4*)d_in[0];
    const float4* e      = (const float4*)d_in[1];
    const int*    t      = (const int*)d_in[2];
    float4* out          = (float4*)d_out;

    const int B = in_sizes[2];
    const int total4 = B * 196;
    const int half = (total4 + 1) / 2;
    const int grid = (half + 255) / 256;

    ddpm_mix_kernel<<<grid, 256>>>(images, e, t, out, half, total4);
}

// round 5
// speedup vs baseline: 1.0025x; 1.0025x over previous
#include <cuda_runtime.h>
#include <cuda_bf16.h>

#define T_STEPS 1000
#define BETA_1 1e-4
#define BETA_T 0.02

// ---- compile-time table: (sqrt(alpha_bar[t]), sqrt(1-alpha_bar[t])) ----

struct ScaleTable {
    float2 v[T_STEPS];
};

constexpr double csqrt(double x) {
    double g = x > 1.0 ? x : 1.0;
    for (int i = 0; i < 60; ++i) g = 0.5 * (g + x / g);
    return g;
}

constexpr ScaleTable make_table() {
    ScaleTable tbl{};
    const double slope = (BETA_T - BETA_1) / (double)(T_STEPS - 1);
    double ab = 1.0;
    for (int i = 0; i < T_STEPS; ++i) {
        double beta = BETA_1 + slope * (double)i;
        ab *= (1.0 - beta);
        tbl.v[i].x = (float)csqrt(ab);
        tbl.v[i].y = (float)csqrt(1.0 - ab);
    }
    return tbl;
}

__constant__ ScaleTable g_scales = make_table();

// ---- mix kernel: 4 float4 per thread (quarter-split), MLP=8, streaming ----
// total4 = B * 196. Thread handles idx + k*quarter for k = 0..3.
// All 8 global loads front-batched; every LDG/STG fully coalesced.

__global__ void __launch_bounds__(256) ddpm_mix_kernel(
    const float4* __restrict__ images,
    const float4* __restrict__ e,
    const int* __restrict__ t,
    float4* __restrict__ out,
    int quarter, int total4)
{
    const int i0 = blockIdx.x * 256 + threadIdx.x;
    if (i0 >= quarter) return;
    const int i1 = i0 + quarter;
    const int i2 = i1 + quarter;
    const int i3 = i2 + quarter;
    const bool h1 = (i1 < total4);
    const bool h2 = (i2 < total4);
    const bool h3 = (i3 < total4);

    // Front-batch all global loads (up to 8 LDG.128 in flight)
    float4 im0 = __ldcs(&images[i0]);
    float4 ee0 = __ldcs(&e[i0]);
    float4 im1, ee1, im2, ee2, im3, ee3;
    if (h1) { im1 = __ldcs(&images[i1]); ee1 = __ldcs(&e[i1]); }
    if (h2) { im2 = __ldcs(&images[i2]); ee2 = __ldcs(&e[i2]); }
    if (h3) { im3 = __ldcs(&images[i3]); ee3 = __ldcs(&e[i3]); }

    {
        const unsigned b = (unsigned)i0 / 196u;
        const float2 sc = g_scales.v[__ldg(&t[b])];
        float4 o;
        o.x = fmaf(sc.x, im0.x, sc.y * ee0.x);
        o.y = fmaf(sc.x, im0.y, sc.y * ee0.y);
        o.z = fmaf(sc.x, im0.z, sc.y * ee0.z);
        o.w = fmaf(sc.x, im0.w, sc.y * ee0.w);
        __stcs(&out[i0], o);
    }
    if (h1) {
        const unsigned b = (unsigned)i1 / 196u;
        const float2 sc = g_scales.v[__ldg(&t[b])];
        float4 o;
        o.x = fmaf(sc.x, im1.x, sc.y * ee1.x);
        o.y = fmaf(sc.x, im1.y, sc.y * ee1.y);
        o.z = fmaf(sc.x, im1.z, sc.y * ee1.z);
        o.w = fmaf(sc.x, im1.w, sc.y * ee1.w);
        __stcs(&out[i1], o);
    }
    if (h2) {
        const unsigned b = (unsigned)i2 / 196u;
        const float2 sc = g_scales.v[__ldg(&t[b])];
        float4 o;
        o.x = fmaf(sc.x, im2.x, sc.y * ee2.x);
        o.y = fmaf(sc.x, im2.y, sc.y * ee2.y);
        o.z = fmaf(sc.x, im2.z, sc.y * ee2.z);
        o.w = fmaf(sc.x, im2.w, sc.y * ee2.w);
        __stcs(&out[i2], o);
    }
    if (h3) {
        const unsigned b = (unsigned)i3 / 196u;
        const float2 sc = g_scales.v[__ldg(&t[b])];
        float4 o;
        o.x = fmaf(sc.x, im3.x, sc.y * ee3.x);
        o.y = fmaf(sc.x, im3.y, sc.y * ee3.y);
        o.z = fmaf(sc.x, im3.z, sc.y * ee3.z);
        o.w = fmaf(sc.x, im3.w, sc.y * ee3.w);
        __stcs(&out[i3], o);
    }
}

extern "C" void kernel_launch(void* const* d_in, const int* in_sizes, int n_in,
                              void* d_out, int out_size) {
    const float4* images = (const float4*)d_in[0];
    const float4* e      = (const float4*)d_in[1];
    const int*    t      = (const int*)d_in[2];
    float4* out          = (float4*)d_out;

    const int B = in_sizes[2];
    const int total4 = B * 196;
    const int quarter = (total4 + 3) / 4;
    const int grid = (quarter + 255) / 256;

    ddpm_mix_kernel<<<grid, 256>>>(images, e, t, out, quarter, total4);
}